// round 9
// baseline (speedup 1.0000x reference)
#include <cuda_runtime.h>
#include <cstdint>

#define MAX_SEG 100001
#define SPB 8            // segments per block
#define NWARP 8          // warps per block (256 threads)
#define SMEM_IDX 2048    // staged indices per block (8 segs, mean ~102 edges)

// scratch (no cudaMalloc allowed)
__device__ int g_offsets[MAX_SEG + 1];

// ---------------------------------------------------------------------------
// Packed-f32 helpers (sm_103a f32x2 pipe) + raw 64-bit global load.
// ---------------------------------------------------------------------------
__device__ __forceinline__ unsigned long long ldg_b64(const void* p) {
    unsigned long long v;
    asm volatile("ld.global.nc.b64 %0, [%1];" : "=l"(v) : "l"(p));
    return v;
}
__device__ __forceinline__ unsigned long long addf32x2(unsigned long long a,
                                                       unsigned long long b) {
    unsigned long long r;
    asm("add.rn.f32x2 %0, %1, %2;" : "=l"(r) : "l"(a), "l"(b));
    return r;
}

// ---------------------------------------------------------------------------
// Inline dtype detection (reference declares int64; JAX w/o x64 emits int32).
// For little-endian int64 indices in [0, 2^31), every odd int32 word is 0.
// For int32 data those words are uniform random gather indices;
// P(first 8 all zero) ~ 1e-42.
// ---------------------------------------------------------------------------
__device__ __forceinline__ bool detect_is64_warp(const void* gidx, int lane) {
    const int* p = (const int*)gidx;
    int w = (lane < 8) ? p[2 * lane + 1] : 0;
    return __all_sync(0xFFFFFFFFu, w == 0);
}

__device__ __forceinline__ int load_idx(const void* p, int i, bool is64) {
    return is64 ? (int)((const long long*)p)[i] : ((const int*)p)[i];
}

// ---------------------------------------------------------------------------
// CSR offsets from sorted segment ids. offsets[s] = first edge with seg >= s.
// ---------------------------------------------------------------------------
__global__ void build_offsets_kernel(const void* __restrict__ seg,
                                     const void* __restrict__ gidx,
                                     int E, int nseg) {
    int e = blockIdx.x * blockDim.x + threadIdx.x;
    bool is64 = detect_is64_warp(gidx, threadIdx.x & 31);
    if (e >= E) return;
    int cur = load_idx(seg, e, is64);
    int prev = (e == 0) ? -1 : load_idx(seg, e - 1, is64);
    for (int s = prev + 1; s <= cur; s++) g_offsets[s] = e;
    if (e == E - 1) {
        for (int s = cur + 1; s <= nseg; s++) g_offsets[s] = E;
    }
}

// ---------------------------------------------------------------------------
// Balanced-block segmented reduction. Block = 8 consecutive segments; its
// contiguous edge range is staged into smem, then split into 8 EQUAL chunks
// (one per warp) regardless of segment boundaries. Each warp accumulates per
// sub-segment (lane owns a float2 slice of the 256B row, f32x2 adds) and
// flushes partials into s_part[warp][seg] (zero-init, each cell written at
// most once -> deterministic). One syncthreads, then warp w combines the 8
// partials of segment w, scales by 1/count, writes the mean.
// ---------------------------------------------------------------------------
__global__ void __launch_bounds__(256)
seg_mean_kernel(const float* __restrict__ values,
                const void* __restrict__ gidx,
                float* __restrict__ out, int nseg) {
    __shared__ int   s_idx[SMEM_IDX];
    __shared__ int   s_off[SPB + 1];
    __shared__ __align__(16) float2 s_part[NWARP][SPB][32];   // 16 KB, 16B-aligned

    int tid  = threadIdx.x;
    int lane = tid & 31;
    int w    = tid >> 5;
    int seg0 = blockIdx.x * SPB;
    bool is64 = detect_is64_warp(gidx, lane);

    if (tid <= SPB) {
        int s = seg0 + tid;
        s_off[tid] = g_offsets[s < nseg ? s : nseg];
    }
    // zero ALL partials: 16KB = NWARP*SPB*32 float2 = 1024 float4
    {
        float4* p = (float4*)s_part;
        #pragma unroll
        for (int i = tid; i < NWARP * SPB * 32 / 2; i += 256)
            p[i] = make_float4(0.f, 0.f, 0.f, 0.f);
    }
    __syncthreads();

    int estart = s_off[0];
    int etot   = s_off[SPB] - estart;
    int nsm    = etot < SMEM_IDX ? etot : SMEM_IDX;

    // coalesced stage of all block indices into smem (int64 -> int32 on load)
    for (int i = tid; i < nsm; i += 256)
        s_idx[i] = load_idx(gidx, estart + i, is64);
    __syncthreads();

    // equal chunk per warp
    int chunk = (etot + NWARP - 1) >> 3;
    int c0 = w * chunk;       if (c0 > etot) c0 = etot;
    int c1 = c0 + chunk;      if (c1 > etot) c1 = etot;

    // first segment whose range contains c0
    int s = 0;
    while (s < SPB && s_off[s + 1] - estart <= c0) s++;

    const char* vb = (const char*)values + lane * 8;  // lane's float2 slot
    bool fast = (etot <= nsm);

    int e = c0;
    while (e < c1 && s < SPB) {
        int segend = s_off[s + 1] - estart;
        if (segend > c1) segend = c1;

        unsigned long long A0 = 0ull, A1 = 0ull, A2 = 0ull, A3 = 0ull;
        if (fast) {
            for (; e + 4 <= segend; e += 4) {
                int i0 = s_idx[e + 0];
                int i1 = s_idx[e + 1];
                int i2 = s_idx[e + 2];
                int i3 = s_idx[e + 3];
                unsigned long long v0 = ldg_b64(vb + (unsigned)i0 * 256u);
                unsigned long long v1 = ldg_b64(vb + (unsigned)i1 * 256u);
                unsigned long long v2 = ldg_b64(vb + (unsigned)i2 * 256u);
                unsigned long long v3 = ldg_b64(vb + (unsigned)i3 * 256u);
                A0 = addf32x2(A0, v0);
                A1 = addf32x2(A1, v1);
                A2 = addf32x2(A2, v2);
                A3 = addf32x2(A3, v3);
            }
            for (; e < segend; e++) {
                unsigned long long v = ldg_b64(vb + (unsigned)s_idx[e] * 256u);
                A0 = addf32x2(A0, v);
            }
        } else {
            // overflow fallback (essentially never taken)
            for (; e < segend; e++) {
                int i0 = (e < nsm) ? s_idx[e] : load_idx(gidx, estart + e, is64);
                unsigned long long v = ldg_b64(vb + (unsigned)i0 * 256u);
                A0 = addf32x2(A0, v);
            }
        }
        unsigned long long S = addf32x2(addf32x2(A0, A1), addf32x2(A2, A3));
        float2 f; f.x = __uint_as_float((unsigned)(S & 0xFFFFFFFFull));
        f.y = __uint_as_float((unsigned)(S >> 32));
        s_part[w][s][lane] = f;
        s++;
    }
    __syncthreads();

    // combine: warp w owns segment w
    int sg = seg0 + w;
    if (sg >= nseg) return;

    unsigned long long S = 0ull;
    #pragma unroll
    for (int ww = 0; ww < NWARP; ww++) {
        float2 f = s_part[ww][w][lane];
        unsigned long long v = ((unsigned long long)__float_as_uint(f.y) << 32)
                             | (unsigned long long)__float_as_uint(f.x);
        S = addf32x2(S, v);
    }
    float sx = __uint_as_float((unsigned)(S & 0xFFFFFFFFull));
    float sy = __uint_as_float((unsigned)(S >> 32));

    int n = s_off[w + 1] - s_off[w];
    float inv = 1.0f / (float)(n > 0 ? n : 1);
    float2 r = {sx * inv, sy * inv};
    ((float2*)(out + (long long)sg * 64))[lane] = r;
}

// ---------------------------------------------------------------------------
// launch
// inputs: 0=values [N_SRC,64] f32, 1=gather_idx [E] i64/i32,
//         2=segment_ids [E] i64/i32 (sorted), 3=num_segments (scalar, unused)
// out: [nseg,64] f32, nseg = out_size/64
// ---------------------------------------------------------------------------
extern "C" void kernel_launch(void* const* d_in, const int* in_sizes, int n_in,
                              void* d_out, int out_size) {
    const float* values = (const float*)d_in[0];
    const void*  gidx   = d_in[1];
    const void*  seg    = d_in[2];
    float* out = (float*)d_out;

    int E    = in_sizes[1];
    int nseg = out_size / 64;
    if (nseg > MAX_SEG) nseg = MAX_SEG;

    int bthreads = 256;
    build_offsets_kernel<<<(E + bthreads - 1) / bthreads, bthreads>>>(seg, gidx, E, nseg);

    int blocks = (nseg + SPB - 1) / SPB;
    seg_mean_kernel<<<blocks, 256>>>(values, gidx, out, nseg);
}

// round 10
// speedup vs baseline: 1.3382x; 1.3382x over previous
#include <cuda_runtime.h>
#include <cstdint>

#define MAX_SEG 100001
#define SEGS_PER_BLOCK 4
#define SMEM_IDX 1024   // indices staged per block (4 segments, mean ~51 edges)

// scratch (no cudaMalloc allowed)
__device__ int g_offsets[MAX_SEG + 1];

// ---------------------------------------------------------------------------
// Packed-f32 helpers (sm_103a f32x2 pipe) + raw 128-bit global load.
// ---------------------------------------------------------------------------
struct U2 { unsigned long long lo, hi; };

__device__ __forceinline__ U2 ldg_b128(const void* p) {
    U2 r;
    asm volatile("ld.global.nc.v2.u64 {%0,%1}, [%2];"
                 : "=l"(r.lo), "=l"(r.hi) : "l"(p));
    return r;
}
__device__ __forceinline__ unsigned long long addf32x2(unsigned long long a,
                                                       unsigned long long b) {
    unsigned long long r;
    asm("add.rn.f32x2 %0, %1, %2;" : "=l"(r) : "l"(a), "l"(b));
    return r;
}

// ---------------------------------------------------------------------------
// Inline dtype detection (reference declares int64; JAX w/o x64 emits int32).
// For little-endian int64 indices in [0, 2^31), every odd int32 word is 0.
// For int32 data those words are uniform random gather indices;
// P(first 8 all zero) ~ 1e-42.
// ---------------------------------------------------------------------------
__device__ __forceinline__ bool detect_is64_warp(const void* gidx, int lane) {
    const int* p = (const int*)gidx;
    int w = (lane < 8) ? p[2 * lane + 1] : 0;
    return __all_sync(0xFFFFFFFFu, w == 0);
}

__device__ __forceinline__ int load_idx(const void* p, int i, bool is64) {
    return is64 ? (int)((const long long*)p)[i] : ((const int*)p)[i];
}

// ---------------------------------------------------------------------------
// CSR offsets from sorted segment ids. offsets[s] = first edge with seg >= s.
// ---------------------------------------------------------------------------
__global__ void build_offsets_kernel(const void* __restrict__ seg,
                                     const void* __restrict__ gidx,
                                     int E, int nseg) {
    int e = blockIdx.x * blockDim.x + threadIdx.x;
    bool is64 = detect_is64_warp(gidx, threadIdx.x & 31);
    if (e >= E) return;
    int cur = load_idx(seg, e, is64);
    int prev = (e == 0) ? -1 : load_idx(seg, e - 1, is64);
    for (int s = prev + 1; s <= cur; s++) g_offsets[s] = e;
    if (e == E - 1) {
        for (int s = cur + 1; s <= nseg; s++) g_offsets[s] = E;
    }
}

// ---------------------------------------------------------------------------
// Block = 4 warps = 4 consecutive segments (contiguous edge range, sorted
// ids). Block stages its gather indices into smem with one coalesced sweep.
// Row loop: lane l16=lane&15 owns a float4 slot of the 256B row; half=lane>>4
// selects row e+half of an edge PAIR -> one LDG.128 fetches TWO gathered
// rows. Per 4 edges: 2 LDS + 2 IMAD.WIDE + 2 LDG.128 + 4 add.f32x2 (~3.25
// warp-instr/edge). Halves combined with 4 shfl_xor(16) per segment.
// ---------------------------------------------------------------------------
__global__ void __launch_bounds__(128)
seg_mean_kernel(const float* __restrict__ values,
                const void* __restrict__ gidx,
                float* __restrict__ out, int nseg) {
    __shared__ int s_idx[SMEM_IDX];
    __shared__ int s_off[SEGS_PER_BLOCK + 1];

    int tid  = threadIdx.x;
    int lane = tid & 31;
    int w    = tid >> 5;
    int seg0 = blockIdx.x * SEGS_PER_BLOCK;
    bool is64 = detect_is64_warp(gidx, lane);

    if (tid <= SEGS_PER_BLOCK) {
        int s = seg0 + tid;
        s_off[tid] = g_offsets[s < nseg ? s : nseg];
    }
    __syncthreads();

    int estart = s_off[0];
    int etot   = s_off[SEGS_PER_BLOCK] - estart;
    int nsm    = etot < SMEM_IDX ? etot : SMEM_IDX;

    // coalesced stage of all block indices into smem (int64 -> int32 on load)
    for (int i = tid; i < nsm; i += 128)
        s_idx[i] = load_idx(gidx, estart + i, is64);
    __syncthreads();

    int seg = seg0 + w;
    if (seg >= nseg) return;

    int start = s_off[w]     - estart;   // block-local edge range
    int end   = s_off[w + 1] - estart;
    int n     = end - start;

    int half = lane >> 4;                // which row of the pair
    int l16  = lane & 15;                // float4 slot within row
    const char* vb = (const char*)values + l16 * 16;

    U2 A0; A0.lo = 0ull; A0.hi = 0ull;   // this half's partial (float4)
    U2 A1; A1.lo = 0ull; A1.hi = 0ull;

    int e = start;
    if (end <= nsm) {
        // main: 4 edges (2 pairs) per iteration
        for (; e + 4 <= end; e += 4) {
            int ia = s_idx[e + half];
            int ib = s_idx[e + 2 + half];
            U2 va = ldg_b128(vb + (unsigned)ia * 256u);
            U2 vc = ldg_b128(vb + (unsigned)ib * 256u);
            A0.lo = addf32x2(A0.lo, va.lo); A0.hi = addf32x2(A0.hi, va.hi);
            A1.lo = addf32x2(A1.lo, vc.lo); A1.hi = addf32x2(A1.hi, vc.hi);
        }
        // one remaining pair
        if (e + 2 <= end) {
            int ia = s_idx[e + half];
            U2 va = ldg_b128(vb + (unsigned)ia * 256u);
            A0.lo = addf32x2(A0.lo, va.lo); A0.hi = addf32x2(A0.hi, va.hi);
            e += 2;
        }
        // single remaining edge: only half 0 contributes
        if (e < end) {
            int ia = s_idx[e];
            U2 va = ldg_b128(vb + (unsigned)ia * 256u);
            if (half == 0) {
                A0.lo = addf32x2(A0.lo, va.lo); A0.hi = addf32x2(A0.hi, va.hi);
            }
        }
    } else {
        // overflow fallback (essentially never taken)
        for (; e < end; e++) {
            int ia = (e < nsm) ? s_idx[e] : load_idx(gidx, estart + e, is64);
            U2 va = ldg_b128(vb + (unsigned)ia * 256u);
            if (half == 0) {
                A0.lo = addf32x2(A0.lo, va.lo); A0.hi = addf32x2(A0.hi, va.hi);
            }
        }
    }

    unsigned long long Slo = addf32x2(A0.lo, A1.lo);
    unsigned long long Shi = addf32x2(A0.hi, A1.hi);

    float f0 = __uint_as_float((unsigned)(Slo & 0xFFFFFFFFull));
    float f1 = __uint_as_float((unsigned)(Slo >> 32));
    float f2 = __uint_as_float((unsigned)(Shi & 0xFFFFFFFFull));
    float f3 = __uint_as_float((unsigned)(Shi >> 32));

    // combine the two halves (same l16 slot, xor lane bit 4)
    f0 += __shfl_xor_sync(0xFFFFFFFFu, f0, 16);
    f1 += __shfl_xor_sync(0xFFFFFFFFu, f1, 16);
    f2 += __shfl_xor_sync(0xFFFFFFFFu, f2, 16);
    f3 += __shfl_xor_sync(0xFFFFFFFFu, f3, 16);

    float inv = 1.0f / (float)(n > 0 ? n : 1);
    if (half == 0) {
        float4 r = {f0 * inv, f1 * inv, f2 * inv, f3 * inv};
        ((float4*)(out + (long long)seg * 64))[l16] = r;
    }
}

// ---------------------------------------------------------------------------
// launch
// inputs: 0=values [N_SRC,64] f32, 1=gather_idx [E] i64/i32,
//         2=segment_ids [E] i64/i32 (sorted), 3=num_segments (scalar, unused)
// out: [nseg,64] f32, nseg = out_size/64
// ---------------------------------------------------------------------------
extern "C" void kernel_launch(void* const* d_in, const int* in_sizes, int n_in,
                              void* d_out, int out_size) {
    const float* values = (const float*)d_in[0];
    const void*  gidx   = d_in[1];
    const void*  seg    = d_in[2];
    float* out = (float*)d_out;

    int E    = in_sizes[1];
    int nseg = out_size / 64;
    if (nseg > MAX_SEG) nseg = MAX_SEG;

    int bthreads = 256;
    build_offsets_kernel<<<(E + bthreads - 1) / bthreads, bthreads>>>(seg, gidx, E, nseg);

    int blocks = (nseg + SEGS_PER_BLOCK - 1) / SEGS_PER_BLOCK;
    seg_mean_kernel<<<blocks, 128>>>(values, gidx, out, nseg);
}